// round 4
// baseline (speedup 1.0000x reference)
#include <cuda_runtime.h>

// Problem dims
constexpr int kS = 96;     // sequence (i and j)
constexpr int kB = 16;     // batch
constexpr int kD = 512;    // embed dim
constexpr int kH = 128;    // hidden
constexpr int kRows = kS * kB;   // 1536 flattened (i,b) rows

constexpr int kSplit = 4;
constexpr int kKChunk = kD / kSplit;   // 128

// Scratch: per-K-split partials, then reduced ha/hb.
__device__ float g_part[kSplit][2][kRows * kH];   // 6.29 MB
__device__ float g_h[2][kRows * kH];              // 1.57 MB

// ---------------------------------------------------------------------------
// Kernel A: partial GEMM.  ha_part[z][r][h] = dot over K-chunk z.
// BM=32, BN=128, BK=32, 256 threads, 4x4 microtile. grid (48, 2, 4) = 384.
// ---------------------------------------------------------------------------
__global__ __launch_bounds__(256) void gemm1_kernel(
    const float* __restrict__ embeds, const float* __restrict__ embeds_cmp,
    const float* __restrict__ W1)
{
    const int which = blockIdx.y;
    const int z     = blockIdx.z;
    const float* src = which ? embeds_cmp : embeds;
    const int wcol = which ? kD : 0;
    float* dst = g_part[z][which];
    const int row0 = blockIdx.x * 32;

    __shared__ float As[32][36];    // [k][m]
    __shared__ float Bs[32][132];   // [k][h]

    const int tid = threadIdx.x;
    const int tx = tid & 31;        // h-group
    const int ty = tid >> 5;        // m-group

    float acc[4][4] = {};

    const int kbeg = z * kKChunk;
    #pragma unroll 1
    for (int k0 = kbeg; k0 < kbeg + kKChunk; k0 += 32) {
        // A tile: 32 rows x 32 k (one float4 per thread)
        {
            int m = tid >> 3, k4 = tid & 7;
            float4 v = *(const float4*)&src[(row0 + m) * kD + k0 + k4 * 4];
            As[k4 * 4 + 0][m] = v.x;
            As[k4 * 4 + 1][m] = v.y;
            As[k4 * 4 + 2][m] = v.z;
            As[k4 * 4 + 3][m] = v.w;
        }
        // B tile: 128 h x 32 k (4 float4 per thread)
        #pragma unroll
        for (int t = 0; t < 4; t++) {
            int idx = tid + t * 256;
            int h = idx >> 3, k4 = idx & 7;
            float4 v = *(const float4*)&W1[h * (2 * kD) + wcol + k0 + k4 * 4];
            Bs[k4 * 4 + 0][h] = v.x;
            Bs[k4 * 4 + 1][h] = v.y;
            Bs[k4 * 4 + 2][h] = v.z;
            Bs[k4 * 4 + 3][h] = v.w;
        }
        __syncthreads();

        #pragma unroll
        for (int kk = 0; kk < 32; kk++) {
            float4 a  = *(const float4*)&As[kk][ty * 4];
            float4 bv = *(const float4*)&Bs[kk][tx * 4];
            float am[4] = {a.x, a.y, a.z, a.w};
            float bn[4] = {bv.x, bv.y, bv.z, bv.w};
            #pragma unroll
            for (int m2 = 0; m2 < 4; m2++)
                #pragma unroll
                for (int n2 = 0; n2 < 4; n2++)
                    acc[m2][n2] = fmaf(am[m2], bn[n2], acc[m2][n2]);
        }
        __syncthreads();
    }

    #pragma unroll
    for (int m2 = 0; m2 < 4; m2++) {
        float4 v = make_float4(acc[m2][0], acc[m2][1], acc[m2][2], acc[m2][3]);
        *(float4*)&dst[(row0 + ty * 4 + m2) * kH + tx * 4] = v;
    }
}

// ---------------------------------------------------------------------------
// Reduce: g_h = sum_z g_part[z].  393216 floats = 98304 float4. 384 blocks.
// ---------------------------------------------------------------------------
__global__ __launch_bounds__(256) void reduce_kernel()
{
    int idx = blockIdx.x * 256 + threadIdx.x;   // float4 index, < 98304
    const float4* p0 = (const float4*)&g_part[0][0][0];
    const float4* p1 = (const float4*)&g_part[1][0][0];
    const float4* p2 = (const float4*)&g_part[2][0][0];
    const float4* p3 = (const float4*)&g_part[3][0][0];
    float4 a = p0[idx], b = p1[idx], c = p2[idx], d = p3[idx];
    float4 r;
    r.x = (a.x + b.x) + (c.x + d.x);
    r.y = (a.y + b.y) + (c.y + d.y);
    r.z = (a.z + b.z) + (c.z + d.z);
    r.w = (a.w + b.w) + (c.w + d.w);
    ((float4*)&g_h[0][0])[idx] = r;
}

// ---------------------------------------------------------------------------
// Kernel B: logits[i,j,b,c] = sum_h relu(ha[i,b,h]+hb[j,b,h]+b1[h]) * W2[c,h] + b2[c]
// Block = 8 i x 32 j x one b.  256 threads: i = tid>>5, j = j0 + (tid&31).
// smem 22 KB -> 4 blocks/SM resident.  grid (12, 3, 16) = 576 blocks.
// ---------------------------------------------------------------------------
__global__ __launch_bounds__(256) void pairwise_kernel(
    const float* __restrict__ b1, const float* __restrict__ W2,
    const float* __restrict__ b2, float* __restrict__ out)
{
    __shared__ float hb_s[32 * 132];   // padded rows: conflict-free LDS.128
    __shared__ float ha_s[8 * 128];    // b1 folded in
    __shared__ float w2_s[256];

    const int b  = blockIdx.z;
    const int i0 = blockIdx.x * 8;
    const int j0 = blockIdx.y * 32;
    const int tid = threadIdx.x;

    // hb tile: 32 j rows x 128 h  (4 float4 per thread)
    #pragma unroll
    for (int t = 0; t < 4; t++) {
        int idx = tid + t * 256;          // 1024 float4s
        int j = idx >> 5, h4 = idx & 31;
        float4 v = *(const float4*)&g_h[1][((j0 + j) * kB + b) * kH + h4 * 4];
        *(float4*)&hb_s[j * 132 + h4 * 4] = v;
    }
    // ha tile + b1 (1 float4 per thread)
    {
        int i = tid >> 5, h4 = tid & 31;
        float4 v  = *(const float4*)&g_h[0][((i0 + i) * kB + b) * kH + h4 * 4];
        float4 bb = *(const float4*)&b1[h4 * 4];
        v.x += bb.x; v.y += bb.y; v.z += bb.z; v.w += bb.w;
        *(float4*)&ha_s[i * 128 + h4 * 4] = v;
    }
    w2_s[tid] = W2[tid];
    const float bias0 = b2[0];
    const float bias1 = b2[1];
    __syncthreads();

    const int tx = tid & 31;
    const int i  = tid >> 5;
    const float* hap = &ha_s[i * 128];
    const float* hbp = &hb_s[tx * 132];

    float acc0 = 0.0f, acc1 = 0.0f;

    #pragma unroll
    for (int h4 = 0; h4 < 32; h4++) {
        float4 a   = *(const float4*)&hap[h4 * 4];          // broadcast
        float4 hv  = *(const float4*)&hbp[h4 * 4];          // lane-distinct
        float4 w0  = *(const float4*)&w2_s[h4 * 4];         // broadcast
        float4 w1v = *(const float4*)&w2_s[128 + h4 * 4];   // broadcast
        float v0 = fmaxf(a.x + hv.x, 0.0f);
        float v1 = fmaxf(a.y + hv.y, 0.0f);
        float v2 = fmaxf(a.z + hv.z, 0.0f);
        float v3 = fmaxf(a.w + hv.w, 0.0f);
        acc0 = fmaf(v0, w0.x, acc0);  acc1 = fmaf(v0, w1v.x, acc1);
        acc0 = fmaf(v1, w0.y, acc0);  acc1 = fmaf(v1, w1v.y, acc1);
        acc0 = fmaf(v2, w0.z, acc0);  acc1 = fmaf(v2, w1v.z, acc1);
        acc0 = fmaf(v3, w0.w, acc0);  acc1 = fmaf(v3, w1v.w, acc1);
    }

    size_t o = ((size_t)((i0 + i) * kS + (j0 + tx)) * kB + b) * 2;
    *(float2*)&out[o] = make_float2(acc0 + bias0, acc1 + bias1);
}

// ---------------------------------------------------------------------------
// Input order (metadata): embeds, umask, qmask, embeds_cmp, W1, b1, W2, b2
// ---------------------------------------------------------------------------
extern "C" void kernel_launch(void* const* d_in, const int* in_sizes, int n_in,
                              void* d_out, int out_size)
{
    const float* embeds     = (const float*)d_in[0];
    const float* embeds_cmp = (const float*)d_in[3];
    const float* W1         = (const float*)d_in[4];
    const float* b1         = (const float*)d_in[5];
    const float* W2         = (const float*)d_in[6];
    const float* b2         = (const float*)d_in[7];
    float* out = (float*)d_out;

    gemm1_kernel<<<dim3(48, 2, kSplit), 256>>>(embeds, embeds_cmp, W1);
    reduce_kernel<<<384, 256>>>();
    pairwise_kernel<<<dim3(12, 3, 16), 256>>>(b1, W2, b2, out);
}

// round 5
// speedup vs baseline: 1.7645x; 1.7645x over previous
#include <cuda_runtime.h>

// Problem dims
constexpr int kS = 96;
constexpr int kB = 16;
constexpr int kD = 512;
constexpr int kH = 128;
constexpr int kRows = kS * kB;   // 1536

constexpr int kSplit = 4;
constexpr int kChunk = kD / kSplit;   // 128

// Per-K-split partials. Pairwise sums them on the fly (no reduce kernel).
__device__ float g_part[kSplit][2][kRows * kH];   // 6.29 MB

// ---------------------------------------------------------------------------
// GEMM: BM=64, BN=128, BK=32, 256 threads, 8x4 microtile, double-buffered.
// grid (24, 2, 4) = 192 blocks.
// ---------------------------------------------------------------------------
constexpr int AS_STRIDE = 68;                 // [kk][m], padded
constexpr int BS_STRIDE = 132;                // [kk][h], padded
constexpr int AS_SZ = 32 * AS_STRIDE;         // 2176 floats
constexpr int BS_SZ = 32 * BS_STRIDE;         // 4224 floats
constexpr int GEMM_SMEM = 2 * (AS_SZ + BS_SZ) * 4;   // 51200 B

__global__ __launch_bounds__(256) void gemm1_kernel(
    const float* __restrict__ embeds, const float* __restrict__ embeds_cmp,
    const float* __restrict__ W1)
{
    extern __shared__ float sm[];
    float* As = sm;                 // [2][32][68]
    float* Bs = sm + 2 * AS_SZ;     // [2][32][132]

    const int which = blockIdx.y;
    const int z     = blockIdx.z;
    const float* src = which ? embeds_cmp : embeds;
    const int wcol = which ? kD : 0;
    float* dst = g_part[z][which];
    const int row0 = blockIdx.x * 64;

    const int tid = threadIdx.x;
    const int tx = tid & 31;        // h-group (4 h each)
    const int ty = tid >> 5;        // m-group (8 m each); constant per warp

    // Load-index precompute
    const int a_m0 = tid >> 3;          // A: idx = tid + t*256 -> m = idx>>3, k4 = idx&7
    const int a_k4 = tid & 7;
    const int b_h0 = tid >> 3;          // B: idx = tid + t*256 -> h = idx>>3, k4 = idx&7
    const int b_k4 = tid & 7;

    float4 pa[2], pb[4];
    float acc[8][4] = {};

    const int kbeg = z * kChunk;

    auto load_tiles = [&](int k0) {
        #pragma unroll
        for (int t = 0; t < 2; t++) {
            int m = a_m0 + t * 32;
            pa[t] = *(const float4*)&src[(row0 + m) * kD + k0 + a_k4 * 4];
        }
        #pragma unroll
        for (int t = 0; t < 4; t++) {
            int h = b_h0 + t * 32;
            pb[t] = *(const float4*)&W1[h * (2 * kD) + wcol + k0 + b_k4 * 4];
        }
    };
    auto store_tiles = [&](int buf) {
        float* A = As + buf * AS_SZ;
        float* B = Bs + buf * BS_SZ;
        #pragma unroll
        for (int t = 0; t < 2; t++) {
            int m = a_m0 + t * 32;
            A[(a_k4 * 4 + 0) * AS_STRIDE + m] = pa[t].x;
            A[(a_k4 * 4 + 1) * AS_STRIDE + m] = pa[t].y;
            A[(a_k4 * 4 + 2) * AS_STRIDE + m] = pa[t].z;
            A[(a_k4 * 4 + 3) * AS_STRIDE + m] = pa[t].w;
        }
        #pragma unroll
        for (int t = 0; t < 4; t++) {
            int h = b_h0 + t * 32;
            B[(b_k4 * 4 + 0) * BS_STRIDE + h] = pb[t].x;
            B[(b_k4 * 4 + 1) * BS_STRIDE + h] = pb[t].y;
            B[(b_k4 * 4 + 2) * BS_STRIDE + h] = pb[t].z;
            B[(b_k4 * 4 + 3) * BS_STRIDE + h] = pb[t].w;
        }
    };
    auto compute = [&](int buf) {
        const float* A = As + buf * AS_SZ + ty * 8;
        const float* B = Bs + buf * BS_SZ + tx * 4;
        #pragma unroll
        for (int kk = 0; kk < 32; kk++) {
            float4 a0 = *(const float4*)&A[kk * AS_STRIDE];       // broadcast
            float4 a1 = *(const float4*)&A[kk * AS_STRIDE + 4];   // broadcast
            float4 bv = *(const float4*)&B[kk * BS_STRIDE];       // 4-phase, no conflict
            float am[8] = {a0.x, a0.y, a0.z, a0.w, a1.x, a1.y, a1.z, a1.w};
            float bn[4] = {bv.x, bv.y, bv.z, bv.w};
            #pragma unroll
            for (int m2 = 0; m2 < 8; m2++)
                #pragma unroll
                for (int n2 = 0; n2 < 4; n2++)
                    acc[m2][n2] = fmaf(am[m2], bn[n2], acc[m2][n2]);
        }
    };

    // Pipelined mainloop over 4 K-tiles
    int buf = 0;
    load_tiles(kbeg);
    store_tiles(0);
    __syncthreads();
    #pragma unroll
    for (int it = 1; it < kChunk / 32; it++) {
        load_tiles(kbeg + it * 32);   // prefetch next
        compute(buf);                 // compute current
        store_tiles(buf ^ 1);
        __syncthreads();
        buf ^= 1;
    }
    compute(buf);

    #pragma unroll
    for (int m2 = 0; m2 < 8; m2++) {
        float4 v = make_float4(acc[m2][0], acc[m2][1], acc[m2][2], acc[m2][3]);
        *(float4*)&dst[(row0 + ty * 8 + m2) * kH + tx * 4] = v;
    }
}

// ---------------------------------------------------------------------------
// Pairwise + fused K-split reduction.
// Block = 8 i x 32 j x one b. grid (12, 3, 16) = 576 blocks, 22 KB smem.
// ---------------------------------------------------------------------------
__global__ __launch_bounds__(256) void pairwise_kernel(
    const float* __restrict__ b1, const float* __restrict__ W2,
    const float* __restrict__ b2, float* __restrict__ out)
{
    __shared__ float hb_s[32 * 132];
    __shared__ float ha_s[8 * 128];
    __shared__ float w2_s[256];

    const int b  = blockIdx.z;
    const int i0 = blockIdx.x * 8;
    const int j0 = blockIdx.y * 32;
    const int tid = threadIdx.x;

    // hb tile with on-the-fly partial sum (4 float4 per thread x 4 partials)
    #pragma unroll
    for (int t = 0; t < 4; t++) {
        int idx = tid + t * 256;
        int j = idx >> 5, h4 = idx & 31;
        int off = ((j0 + j) * kB + b) * kH + h4 * 4;
        float4 s = make_float4(0.f, 0.f, 0.f, 0.f);
        #pragma unroll
        for (int zz = 0; zz < kSplit; zz++) {
            float4 v = *(const float4*)&g_part[zz][1][off];
            s.x += v.x; s.y += v.y; s.z += v.z; s.w += v.w;
        }
        *(float4*)&hb_s[j * 132 + h4 * 4] = s;
    }
    // ha tile: partial sum + b1
    {
        int i = tid >> 5, h4 = tid & 31;
        int off = ((i0 + i) * kB + b) * kH + h4 * 4;
        float4 s = *(const float4*)&b1[h4 * 4];
        #pragma unroll
        for (int zz = 0; zz < kSplit; zz++) {
            float4 v = *(const float4*)&g_part[zz][0][off];
            s.x += v.x; s.y += v.y; s.z += v.z; s.w += v.w;
        }
        *(float4*)&ha_s[i * 128 + h4 * 4] = s;
    }
    w2_s[tid] = W2[tid];
    const float bias0 = b2[0];
    const float bias1 = b2[1];
    __syncthreads();

    const int tx = tid & 31;
    const int i  = tid >> 5;
    const float* hap = &ha_s[i * 128];
    const float* hbp = &hb_s[tx * 132];

    float acc0 = 0.0f, acc1 = 0.0f;

    #pragma unroll
    for (int h4 = 0; h4 < 32; h4++) {
        float4 a   = *(const float4*)&hap[h4 * 4];
        float4 hv  = *(const float4*)&hbp[h4 * 4];
        float4 w0  = *(const float4*)&w2_s[h4 * 4];
        float4 w1v = *(const float4*)&w2_s[128 + h4 * 4];
        float v0 = fmaxf(a.x + hv.x, 0.0f);
        float v1 = fmaxf(a.y + hv.y, 0.0f);
        float v2 = fmaxf(a.z + hv.z, 0.0f);
        float v3 = fmaxf(a.w + hv.w, 0.0f);
        acc0 = fmaf(v0, w0.x, acc0);  acc1 = fmaf(v0, w1v.x, acc1);
        acc0 = fmaf(v1, w0.y, acc0);  acc1 = fmaf(v1, w1v.y, acc1);
        acc0 = fmaf(v2, w0.z, acc0);  acc1 = fmaf(v2, w1v.z, acc1);
        acc0 = fmaf(v3, w0.w, acc0);  acc1 = fmaf(v3, w1v.w, acc1);
    }

    size_t o = ((size_t)((i0 + i) * kS + (j0 + tx)) * kB + b) * 2;
    *(float2*)&out[o] = make_float2(acc0 + bias0, acc1 + bias1);
}

// ---------------------------------------------------------------------------
// Input order: embeds, umask, qmask, embeds_cmp, W1, b1, W2, b2
// ---------------------------------------------------------------------------
extern "C" void kernel_launch(void* const* d_in, const int* in_sizes, int n_in,
                              void* d_out, int out_size)
{
    const float* embeds     = (const float*)d_in[0];
    const float* embeds_cmp = (const float*)d_in[3];
    const float* W1         = (const float*)d_in[4];
    const float* b1         = (const float*)d_in[5];
    const float* W2         = (const float*)d_in[6];
    const float* b2         = (const float*)d_in[7];
    float* out = (float*)d_out;

    static bool attr_set = false;
    if (!attr_set) {
        cudaFuncSetAttribute(gemm1_kernel,
                             cudaFuncAttributeMaxDynamicSharedMemorySize, GEMM_SMEM);
        attr_set = true;
    }

    gemm1_kernel<<<dim3(24, 2, kSplit), 256, GEMM_SMEM>>>(embeds, embeds_cmp, W1);
    pairwise_kernel<<<dim3(12, 3, 16), 256>>>(b1, W2, b2, out);
}

// round 11
// speedup vs baseline: 2.1430x; 1.2146x over previous
#include <cuda_runtime.h>

// Problem dims
constexpr int kS = 96;
constexpr int kB = 16;
constexpr int kD = 512;
constexpr int kH = 128;
constexpr int kRows = kS * kB;   // 1536

constexpr int kSplit = 3;        // uneven K-split: 192/160/160

// Per-K-split partials; pairwise sums them on the fly.
__device__ float g_part[kSplit][2][kRows * kH];   // 4.7 MB

// ---------------------------------------------------------------------------
// GEMM: BM=64, BN=128, BK=32, 256 threads, 8x4 microtile, double-buffered.
// grid (24, 2, 3) = 144 blocks = one full wave.
// ---------------------------------------------------------------------------
constexpr int AS_STRIDE = 68;
constexpr int BS_STRIDE = 132;
constexpr int AS_SZ = 32 * AS_STRIDE;
constexpr int BS_SZ = 32 * BS_STRIDE;
constexpr int GEMM_SMEM = 2 * (AS_SZ + BS_SZ) * 4;   // 51200 B

__global__ __launch_bounds__(256) void gemm1_kernel(
    const float* __restrict__ embeds, const float* __restrict__ embeds_cmp,
    const float* __restrict__ W1)
{
    extern __shared__ float sm[];
    float* As = sm;                 // [2][32][68]
    float* Bs = sm + 2 * AS_SZ;     // [2][32][132]

    const int which = blockIdx.y;
    const int z     = blockIdx.z;
    const float* src = which ? embeds_cmp : embeds;
    const int wcol = which ? kD : 0;
    float* dst = g_part[z][which];
    const int row0 = blockIdx.x * 64;

    // Uneven split: tiles-of-32 counts 6/5/5, starts 0/192/352
    const int kbeg  = (z == 0) ? 0 : (z == 1 ? 192 : 352);
    const int nIter = (z == 0) ? 6 : 5;

    const int tid = threadIdx.x;
    const int tx = tid & 31;
    const int ty = tid >> 5;

    const int a_m0 = tid >> 3;
    const int a_k4 = tid & 7;

    float4 pa[2], pb[4];
    float acc[8][4] = {};

    auto load_tiles = [&](int k0) {
        #pragma unroll
        for (int t = 0; t < 2; t++) {
            int m = a_m0 + t * 32;
            pa[t] = *(const float4*)&src[(row0 + m) * kD + k0 + a_k4 * 4];
        }
        #pragma unroll
        for (int t = 0; t < 4; t++) {
            int h = a_m0 + t * 32;
            pb[t] = *(const float4*)&W1[h * (2 * kD) + wcol + k0 + a_k4 * 4];
        }
    };
    auto store_tiles = [&](int buf) {
        float* A = As + buf * AS_SZ;
        float* B = Bs + buf * BS_SZ;
        #pragma unroll
        for (int t = 0; t < 2; t++) {
            int m = a_m0 + t * 32;
            A[(a_k4 * 4 + 0) * AS_STRIDE + m] = pa[t].x;
            A[(a_k4 * 4 + 1) * AS_STRIDE + m] = pa[t].y;
            A[(a_k4 * 4 + 2) * AS_STRIDE + m] = pa[t].z;
            A[(a_k4 * 4 + 3) * AS_STRIDE + m] = pa[t].w;
        }
        #pragma unroll
        for (int t = 0; t < 4; t++) {
            int h = a_m0 + t * 32;
            B[(a_k4 * 4 + 0) * BS_STRIDE + h] = pb[t].x;
            B[(a_k4 * 4 + 1) * BS_STRIDE + h] = pb[t].y;
            B[(a_k4 * 4 + 2) * BS_STRIDE + h] = pb[t].z;
            B[(a_k4 * 4 + 3) * BS_STRIDE + h] = pb[t].w;
        }
    };
    auto compute = [&](int buf) {
        const float* A = As + buf * AS_SZ + ty * 8;
        const float* B = Bs + buf * BS_SZ + tx * 4;
        #pragma unroll
        for (int kk = 0; kk < 32; kk++) {
            float4 a0 = *(const float4*)&A[kk * AS_STRIDE];
            float4 a1 = *(const float4*)&A[kk * AS_STRIDE + 4];
            float4 bv = *(const float4*)&B[kk * BS_STRIDE];
            float am[8] = {a0.x, a0.y, a0.z, a0.w, a1.x, a1.y, a1.z, a1.w};
            float bn[4] = {bv.x, bv.y, bv.z, bv.w};
            #pragma unroll
            for (int m2 = 0; m2 < 8; m2++)
                #pragma unroll
                for (int n2 = 0; n2 < 4; n2++)
                    acc[m2][n2] = fmaf(am[m2], bn[n2], acc[m2][n2]);
        }
    };

    int buf = 0;
    load_tiles(kbeg);
    store_tiles(0);
    __syncthreads();
    for (int it = 1; it < nIter; it++) {
        load_tiles(kbeg + it * 32);
        compute(buf);
        store_tiles(buf ^ 1);
        __syncthreads();
        buf ^= 1;
    }
    compute(buf);

    #pragma unroll
    for (int m2 = 0; m2 < 8; m2++) {
        float4 v = make_float4(acc[m2][0], acc[m2][1], acc[m2][2], acc[m2][3]);
        *(float4*)&dst[(row0 + ty * 8 + m2) * kH + tx * 4] = v;
    }
}

// ---------------------------------------------------------------------------
// Pairwise + fused 3-partial reduction.
// Block = 16 i x 32 j x one b; each warp owns 2 i-rows, lane = j.
// grid (6, 3, 16) = 288 blocks, ~26 KB smem -> 2+ blocks/SM.
// ---------------------------------------------------------------------------
__global__ __launch_bounds__(256) void pairwise_kernel(
    const float* __restrict__ b1, const float* __restrict__ W2,
    const float* __restrict__ b2, float* __restrict__ out)
{
    __shared__ float hb_s[32 * 132];
    __shared__ float ha_s[16 * 128];
    __shared__ float w2_s[256];

    const int b  = blockIdx.z;
    const int i0 = blockIdx.x * 16;
    const int j0 = blockIdx.y * 32;
    const int tid = threadIdx.x;

    // hb tile (32 j-rows), summing 3 partials
    #pragma unroll
    for (int t = 0; t < 4; t++) {
        int idx = tid + t * 256;
        int j = idx >> 5, h4 = idx & 31;
        int off = ((j0 + j) * kB + b) * kH + h4 * 4;
        float4 v0 = *(const float4*)&g_part[0][1][off];
        float4 v1 = *(const float4*)&g_part[1][1][off];
        float4 v2 = *(const float4*)&g_part[2][1][off];
        float4 s;
        s.x = v0.x + v1.x + v2.x;  s.y = v0.y + v1.y + v2.y;
        s.z = v0.z + v1.z + v2.z;  s.w = v0.w + v1.w + v2.w;
        *(float4*)&hb_s[j * 132 + h4 * 4] = s;
    }
    // ha tile (16 i-rows), summing 3 partials + b1
    #pragma unroll
    for (int t = 0; t < 2; t++) {
        int idx = tid + t * 256;
        int i = idx >> 5, h4 = idx & 31;
        int off = ((i0 + i) * kB + b) * kH + h4 * 4;
        float4 s  = *(const float4*)&b1[h4 * 4];
        float4 v0 = *(const float4*)&g_part[0][0][off];
        float4 v1 = *(const float4*)&g_part[1][0][off];
        float4 v2 = *(const float4*)&g_part[2][0][off];
        s.x += v0.x + v1.x + v2.x;  s.y += v0.y + v1.y + v2.y;
        s.z += v0.z + v1.z + v2.z;  s.w += v0.w + v1.w + v2.w;
        *(float4*)&ha_s[i * 128 + h4 * 4] = s;
    }
    w2_s[tid] = W2[tid];
    const float bias0 = b2[0];
    const float bias1 = b2[1];
    __syncthreads();

    const int lane = tid & 31;
    const int w    = tid >> 5;
    const float* hap0 = &ha_s[(w * 2 + 0) * 128];
    const float* hap1 = &ha_s[(w * 2 + 1) * 128];
    const float* hbp  = &hb_s[lane * 132];

    float acc00 = 0.f, acc01 = 0.f, acc10 = 0.f, acc11 = 0.f;

    #pragma unroll 8
    for (int h4 = 0; h4 < 32; h4++) {
        float4 hv = *(const float4*)&hbp[h4 * 4];          // lane-distinct
        float4 a0 = *(const float4*)&hap0[h4 * 4];         // broadcast
        float4 a1 = *(const float4*)&hap1[h4 * 4];         // broadcast
        float4 w0 = *(const float4*)&w2_s[h4 * 4];         // broadcast
        float4 w1 = *(const float4*)&w2_s[128 + h4 * 4];   // broadcast

        float u0 = fmaxf(a0.x + hv.x, 0.f);
        float u1 = fmaxf(a0.y + hv.y, 0.f);
        float u2 = fmaxf(a0.z + hv.z, 0.f);
        float u3 = fmaxf(a0.w + hv.w, 0.f);
        acc00 = fmaf(u0, w0.x, acc00);  acc01 = fmaf(u0, w1.x, acc01);
        acc00 = fmaf(u1, w0.y, acc00);  acc01 = fmaf(u1, w1.y, acc01);
        acc00 = fmaf(u2, w0.z, acc00);  acc01 = fmaf(u2, w1.z, acc01);
        acc00 = fmaf(u3, w0.w, acc00);  acc01 = fmaf(u3, w1.w, acc01);

        float t0 = fmaxf(a1.x + hv.x, 0.f);
        float t1 = fmaxf(a1.y + hv.y, 0.f);
        float t2 = fmaxf(a1.z + hv.z, 0.f);
        float t3 = fmaxf(a1.w + hv.w, 0.f);
        acc10 = fmaf(t0, w0.x, acc10);  acc11 = fmaf(t0, w1.x, acc11);
        acc10 = fmaf(t1, w0.y, acc10);  acc11 = fmaf(t1, w1.y, acc11);
        acc10 = fmaf(t2, w0.z, acc10);  acc11 = fmaf(t2, w1.z, acc11);
        acc10 = fmaf(t3, w0.w, acc10);  acc11 = fmaf(t3, w1.w, acc11);
    }

    const int i  = i0 + w * 2;
    const int j  = j0 + lane;
    size_t o0 = ((size_t)(i * kS + j) * kB + b) * 2;
    size_t o1 = ((size_t)((i + 1) * kS + j) * kB + b) * 2;
    *(float2*)&out[o0] = make_float2(acc00 + bias0, acc01 + bias1);
    *(float2*)&out[o1] = make_float2(acc10 + bias0, acc11 + bias1);
}

// ---------------------------------------------------------------------------
// Input order: embeds, umask, qmask, embeds_cmp, W1, b1, W2, b2
// ---------------------------------------------------------------------------
extern "C" void kernel_launch(void* const* d_in, const int* in_sizes, int n_in,
                              void* d_out, int out_size)
{
    const float* embeds     = (const float*)d_in[0];
    const float* embeds_cmp = (const float*)d_in[3];
    const float* W1         = (const float*)d_in[4];
    const float* b1         = (const float*)d_in[5];
    const float* W2         = (const float*)d_in[6];
    const float* b2         = (const float*)d_in[7];
    float* out = (float*)d_out;

    cudaFuncSetAttribute(gemm1_kernel,
                         cudaFuncAttributeMaxDynamicSharedMemorySize, GEMM_SMEM);

    gemm1_kernel<<<dim3(24, 2, kSplit), 256, GEMM_SMEM>>>(embeds, embeds_cmp, W1);
    pairwise_kernel<<<dim3(6, 3, 16), 256>>>(b1, W2, b2, out);
}

// round 12
// speedup vs baseline: 2.8060x; 1.3094x over previous
#include <cuda_runtime.h>
#include <cstdint>

// Problem dims
constexpr int kS = 96;
constexpr int kB = 16;
constexpr int kD = 512;
constexpr int kH = 128;
constexpr int kRows = kS * kB;   // 1536

constexpr int kSplit = 3;        // uneven K-split: 192/160/160

// Per-K-split partials; pairwise sums them on the fly.
__device__ float g_part[kSplit][2][kRows * kH];   // 4.7 MB

// ---------------------------------------------------------------------------
// GEMM via tf32 mma.sync.m16n8k8.
// BM=64, BN=128 (all h), BK=32 per stage, 256 threads = 8 warps (2 m x 4 n),
// warp tile 32m x 32n. Double-buffered smem. grid (24, 2, 3) = 144 = 1 wave.
// smem: A[64][36] + B[128][36] per buffer (stride 36 = 4 mod 32 -> frag LDS
// addresses 4*gid+tig hit all 32 banks, conflict-free).
// ---------------------------------------------------------------------------
constexpr int AS_STRIDE = 36;
constexpr int BS_STRIDE = 36;
constexpr int AS_SZ = 64 * AS_STRIDE;    // 2304 floats
constexpr int BS_SZ = 128 * BS_STRIDE;   // 4608 floats
constexpr int GEMM_SMEM = 2 * (AS_SZ + BS_SZ) * 4;   // 55296 B

__device__ __forceinline__ uint32_t f2tf32(float x) {
    uint32_t r;
    asm("cvt.rna.tf32.f32 %0, %1;" : "=r"(r) : "f"(x));
    return r;
}

__device__ __forceinline__ void mma_tf32(
    float& c0, float& c1, float& c2, float& c3,
    uint32_t a0, uint32_t a1, uint32_t a2, uint32_t a3,
    uint32_t b0, uint32_t b1)
{
    asm volatile(
        "mma.sync.aligned.m16n8k8.row.col.f32.tf32.tf32.f32 "
        "{%0,%1,%2,%3}, {%4,%5,%6,%7}, {%8,%9}, {%0,%1,%2,%3};"
        : "+f"(c0), "+f"(c1), "+f"(c2), "+f"(c3)
        : "r"(a0), "r"(a1), "r"(a2), "r"(a3), "r"(b0), "r"(b1));
}

__global__ __launch_bounds__(256) void gemm1_kernel(
    const float* __restrict__ embeds, const float* __restrict__ embeds_cmp,
    const float* __restrict__ W1)
{
    extern __shared__ float sm[];
    uint32_t* As = (uint32_t*)sm;                 // [2][64][36] tf32 bits
    uint32_t* Bs = (uint32_t*)(sm + 2 * AS_SZ);   // [2][128][36]

    const int which = blockIdx.y;
    const int z     = blockIdx.z;
    const float* src = which ? embeds_cmp : embeds;
    const int wcol = which ? kD : 0;
    float* dst = g_part[z][which];
    const int row0 = blockIdx.x * 64;

    // Uneven split: stage counts 6/5/5 of BK=32, starts 0/192/352
    const int kbeg  = (z == 0) ? 0 : (z == 1 ? 192 : 352);
    const int nIter = (z == 0) ? 6 : 5;

    const int tid  = threadIdx.x;
    const int wid  = tid >> 5;
    const int lane = tid & 31;
    const int gid  = lane >> 2;     // 0..7
    const int tig  = lane & 3;      // 0..3
    const int warp_m = wid & 1;     // 2 m-warps
    const int warp_n = wid >> 1;    // 4 n-warps

    const int a_m0 = tid >> 3;      // 0..31
    const int a_k4 = tid & 7;       // 0..7  (k offset = 4*a_k4)

    float4 pa[2], pb[4];
    float acc[2][4][4] = {};        // [m-tile][n-tile][c0..c3]

    auto load_tiles = [&](int k0) {
        #pragma unroll
        for (int t = 0; t < 2; t++) {
            int m = a_m0 + t * 32;
            pa[t] = *(const float4*)&src[(row0 + m) * kD + k0 + a_k4 * 4];
        }
        #pragma unroll
        for (int t = 0; t < 4; t++) {
            int h = a_m0 + t * 32;
            pb[t] = *(const float4*)&W1[h * (2 * kD) + wcol + k0 + a_k4 * 4];
        }
    };
    auto store_tiles = [&](int buf) {
        uint32_t* A = As + buf * AS_SZ;
        uint32_t* B = Bs + buf * BS_SZ;
        #pragma unroll
        for (int t = 0; t < 2; t++) {
            int m = a_m0 + t * 32;
            uint32_t* p = &A[m * AS_STRIDE + a_k4 * 4];
            p[0] = f2tf32(pa[t].x);
            p[1] = f2tf32(pa[t].y);
            p[2] = f2tf32(pa[t].z);
            p[3] = f2tf32(pa[t].w);
        }
        #pragma unroll
        for (int t = 0; t < 4; t++) {
            int h = a_m0 + t * 32;
            uint32_t* p = &B[h * BS_STRIDE + a_k4 * 4];
            p[0] = f2tf32(pb[t].x);
            p[1] = f2tf32(pb[t].y);
            p[2] = f2tf32(pb[t].z);
            p[3] = f2tf32(pb[t].w);
        }
    };
    auto compute = [&](int buf) {
        const uint32_t* A = As + buf * AS_SZ;
        const uint32_t* B = Bs + buf * BS_SZ;
        #pragma unroll
        for (int kk8 = 0; kk8 < 4; kk8++) {
            const int kb = kk8 * 8;
            // A fragments: 2 m-tiles (m16 each)
            uint32_t af[2][4];
            #pragma unroll
            for (int t = 0; t < 2; t++) {
                int rbase = warp_m * 32 + t * 16;
                const uint32_t* ap = &A[(rbase + gid) * AS_STRIDE + kb + tig];
                af[t][0] = ap[0];
                af[t][1] = ap[8 * AS_STRIDE];
                af[t][2] = ap[4];
                af[t][3] = ap[8 * AS_STRIDE + 4];
            }
            // B fragments: 4 n-tiles (n8 each)
            uint32_t bf[4][2];
            #pragma unroll
            for (int n = 0; n < 4; n++) {
                int nb = warp_n * 32 + n * 8;
                const uint32_t* bp = &B[(nb + gid) * BS_STRIDE + kb + tig];
                bf[n][0] = bp[0];
                bf[n][1] = bp[4];
            }
            #pragma unroll
            for (int t = 0; t < 2; t++)
                #pragma unroll
                for (int n = 0; n < 4; n++)
                    mma_tf32(acc[t][n][0], acc[t][n][1], acc[t][n][2], acc[t][n][3],
                             af[t][0], af[t][1], af[t][2], af[t][3],
                             bf[n][0], bf[n][1]);
        }
    };

    int buf = 0;
    load_tiles(kbeg);
    store_tiles(0);
    __syncthreads();
    for (int it = 1; it < nIter; it++) {
        load_tiles(kbeg + it * 32);
        compute(buf);
        store_tiles(buf ^ 1);
        __syncthreads();
        buf ^= 1;
    }
    compute(buf);

    // Epilogue: c0/c1 -> (row, 2*tig), c2/c3 -> (row+8, 2*tig)
    #pragma unroll
    for (int t = 0; t < 2; t++) {
        int r0 = row0 + warp_m * 32 + t * 16 + gid;
        #pragma unroll
        for (int n = 0; n < 4; n++) {
            int c = warp_n * 32 + n * 8 + 2 * tig;
            *(float2*)&dst[r0 * kH + c]       = make_float2(acc[t][n][0], acc[t][n][1]);
            *(float2*)&dst[(r0 + 8) * kH + c] = make_float2(acc[t][n][2], acc[t][n][3]);
        }
    }
}

// ---------------------------------------------------------------------------
// Pairwise + fused 3-partial reduction (unchanged from R11).
// Block = 16 i x 32 j x one b; each warp owns 2 i-rows, lane = j.
// grid (6, 3, 16) = 288 blocks.
// ---------------------------------------------------------------------------
__global__ __launch_bounds__(256) void pairwise_kernel(
    const float* __restrict__ b1, const float* __restrict__ W2,
    const float* __restrict__ b2, float* __restrict__ out)
{
    __shared__ float hb_s[32 * 132];
    __shared__ float ha_s[16 * 128];
    __shared__ float w2_s[256];

    const int b  = blockIdx.z;
    const int i0 = blockIdx.x * 16;
    const int j0 = blockIdx.y * 32;
    const int tid = threadIdx.x;

    #pragma unroll
    for (int t = 0; t < 4; t++) {
        int idx = tid + t * 256;
        int j = idx >> 5, h4 = idx & 31;
        int off = ((j0 + j) * kB + b) * kH + h4 * 4;
        float4 v0 = *(const float4*)&g_part[0][1][off];
        float4 v1 = *(const float4*)&g_part[1][1][off];
        float4 v2 = *(const float4*)&g_part[2][1][off];
        float4 s;
        s.x = v0.x + v1.x + v2.x;  s.y = v0.y + v1.y + v2.y;
        s.z = v0.z + v1.z + v2.z;  s.w = v0.w + v1.w + v2.w;
        *(float4*)&hb_s[j * 132 + h4 * 4] = s;
    }
    #pragma unroll
    for (int t = 0; t < 2; t++) {
        int idx = tid + t * 256;
        int i = idx >> 5, h4 = idx & 31;
        int off = ((i0 + i) * kB + b) * kH + h4 * 4;
        float4 s  = *(const float4*)&b1[h4 * 4];
        float4 v0 = *(const float4*)&g_part[0][0][off];
        float4 v1 = *(const float4*)&g_part[1][0][off];
        float4 v2 = *(const float4*)&g_part[2][0][off];
        s.x += v0.x + v1.x + v2.x;  s.y += v0.y + v1.y + v2.y;
        s.z += v0.z + v1.z + v2.z;  s.w += v0.w + v1.w + v2.w;
        *(float4*)&ha_s[i * 128 + h4 * 4] = s;
    }
    w2_s[tid] = W2[tid];
    const float bias0 = b2[0];
    const float bias1 = b2[1];
    __syncthreads();

    const int lane = tid & 31;
    const int w    = tid >> 5;
    const float* hap0 = &ha_s[(w * 2 + 0) * 128];
    const float* hap1 = &ha_s[(w * 2 + 1) * 128];
    const float* hbp  = &hb_s[lane * 132];

    float acc00 = 0.f, acc01 = 0.f, acc10 = 0.f, acc11 = 0.f;

    #pragma unroll 8
    for (int h4 = 0; h4 < 32; h4++) {
        float4 hv = *(const float4*)&hbp[h4 * 4];
        float4 a0 = *(const float4*)&hap0[h4 * 4];
        float4 a1 = *(const float4*)&hap1[h4 * 4];
        float4 w0 = *(const float4*)&w2_s[h4 * 4];
        float4 w1 = *(const float4*)&w2_s[128 + h4 * 4];

        float u0 = fmaxf(a0.x + hv.x, 0.f);
        float u1 = fmaxf(a0.y + hv.y, 0.f);
        float u2 = fmaxf(a0.z + hv.z, 0.f);
        float u3 = fmaxf(a0.w + hv.w, 0.f);
        acc00 = fmaf(u0, w0.x, acc00);  acc01 = fmaf(u0, w1.x, acc01);
        acc00 = fmaf(u1, w0.y, acc00);  acc01 = fmaf(u1, w1.y, acc01);
        acc00 = fmaf(u2, w0.z, acc00);  acc01 = fmaf(u2, w1.z, acc01);
        acc00 = fmaf(u3, w0.w, acc00);  acc01 = fmaf(u3, w1.w, acc01);

        float t0 = fmaxf(a1.x + hv.x, 0.f);
        float t1 = fmaxf(a1.y + hv.y, 0.f);
        float t2 = fmaxf(a1.z + hv.z, 0.f);
        float t3 = fmaxf(a1.w + hv.w, 0.f);
        acc10 = fmaf(t0, w0.x, acc10);  acc11 = fmaf(t0, w1.x, acc11);
        acc10 = fmaf(t1, w0.y, acc10);  acc11 = fmaf(t1, w1.y, acc11);
        acc10 = fmaf(t2, w0.z, acc10);  acc11 = fmaf(t2, w1.z, acc11);
        acc10 = fmaf(t3, w0.w, acc10);  acc11 = fmaf(t3, w1.w, acc11);
    }

    const int i  = i0 + w * 2;
    const int j  = j0 + lane;
    size_t o0 = ((size_t)(i * kS + j) * kB + b) * 2;
    size_t o1 = ((size_t)((i + 1) * kS + j) * kB + b) * 2;
    *(float2*)&out[o0] = make_float2(acc00 + bias0, acc01 + bias1);
    *(float2*)&out[o1] = make_float2(acc10 + bias0, acc11 + bias1);
}

// ---------------------------------------------------------------------------
// Input order: embeds, umask, qmask, embeds_cmp, W1, b1, W2, b2
// ---------------------------------------------------------------------------
extern "C" void kernel_launch(void* const* d_in, const int* in_sizes, int n_in,
                              void* d_out, int out_size)
{
    const float* embeds     = (const float*)d_in[0];
    const float* embeds_cmp = (const float*)d_in[3];
    const float* W1         = (const float*)d_in[4];
    const float* b1         = (const float*)d_in[5];
    const float* W2         = (const float*)d_in[6];
    const float* b2         = (const float*)d_in[7];
    float* out = (float*)d_out;

    cudaFuncSetAttribute(gemm1_kernel,
                         cudaFuncAttributeMaxDynamicSharedMemorySize, GEMM_SMEM);

    gemm1_kernel<<<dim3(24, 2, kSplit), 256, GEMM_SMEM>>>(embeds, embeds_cmp, W1);
    pairwise_kernel<<<dim3(6, 3, 16), 256>>>(b1, W2, b2, out);
}